// round 4
// baseline (speedup 1.0000x reference)
#include <cuda_runtime.h>
#include <cuda_bf16.h>
#include <cstdint>

#define B_    32
#define NTOK  3136
#define NH    12
#define D_    32

// ---------------- scratch (device globals; no allocation allowed) -------------
__device__ __align__(16) float g_Q[(size_t)B_ * NH * NTOK * D_];   // [b*12+h][n][d]
__device__ __align__(16) float g_K[(size_t)B_ * NH * NTOK * D_];
__device__ __align__(16) float g_V[(size_t)B_ * NH * NTOK * D_];
__device__ __align__(16) float g_Q1[B_ * 4 * 784 * D_];
__device__ __align__(16) float g_K1[B_ * 4 * 784 * D_];
__device__ __align__(16) float g_V1[B_ * 4 * 784 * D_];
__device__ __align__(16) float g_Q2[B_ * 4 * 196 * D_];
__device__ __align__(16) float g_K2[B_ * 4 * 196 * D_];
__device__ __align__(16) float g_V2[B_ * 4 * 196 * D_];

#define XELEMS ((size_t)B_ * NTOK * 384)
__device__ __align__(16) __nv_bfloat16 g_Xh[XELEMS];
__device__ __align__(16) __nv_bfloat16 g_Xl[XELEMS];
__device__ __align__(16) __nv_bfloat16 g_Zh[XELEMS];
__device__ __align__(16) __nv_bfloat16 g_Zl[XELEMS];
// transposed weights, [n][k]: rows 0..1151 = qkv output cols, 1152..1535 = proj cols
__device__ __align__(16) __nv_bfloat16 g_WTh[1536 * 384];
__device__ __align__(16) __nv_bfloat16 g_WTl[1536 * 384];

// ---------------- helpers -------------------------------------------------------
__device__ __forceinline__ uint32_t smem_u32(const void* p) {
    uint32_t a;
    asm("{ .reg .u64 t; cvta.to.shared.u64 t, %1; cvt.u32.u64 %0, t; }" : "=r"(a) : "l"(p));
    return a;
}
__device__ __forceinline__ void cp16(uint32_t dst, const void* src) {
    asm volatile("cp.async.cg.shared.global [%0], [%1], 16;" :: "r"(dst), "l"(src));
}
__device__ __forceinline__ void ldm_x4(uint32_t* r, uint32_t a) {
    asm volatile("ldmatrix.sync.aligned.m8n8.x4.shared.b16 {%0,%1,%2,%3}, [%4];"
                 : "=r"(r[0]), "=r"(r[1]), "=r"(r[2]), "=r"(r[3]) : "r"(a));
}
__device__ __forceinline__ void mma16816(float* d, const uint32_t* a, const uint32_t* b) {
    asm volatile(
        "mma.sync.aligned.m16n8k16.row.col.f32.bf16.bf16.f32 "
        "{%0,%1,%2,%3}, {%4,%5,%6,%7}, {%8,%9}, {%0,%1,%2,%3};"
        : "+f"(d[0]), "+f"(d[1]), "+f"(d[2]), "+f"(d[3])
        : "r"(a[0]), "r"(a[1]), "r"(a[2]), "r"(a[3]), "r"(b[0]), "r"(b[1]));
}

// ---------------- split / transpose kernels ------------------------------------
__global__ void split_x(const float4* __restrict__ src) {
    uint2* hiP = (uint2*)g_Xh;
    uint2* loP = (uint2*)g_Xl;
    const int n4 = (int)(XELEMS / 4);
    const int stride = gridDim.x * blockDim.x;
    for (int i = blockIdx.x * blockDim.x + threadIdx.x; i < n4; i += stride) {
        float4 f = src[i];
        uint32_t x = __float_as_uint(f.x), y = __float_as_uint(f.y);
        uint32_t z = __float_as_uint(f.z), w = __float_as_uint(f.w);
        uint2 h;
        h.x = __byte_perm(x, y, 0x7632);
        h.y = __byte_perm(z, w, 0x7632);
        float l0 = f.x - __uint_as_float(x & 0xFFFF0000u);
        float l1 = f.y - __uint_as_float(y & 0xFFFF0000u);
        float l2 = f.z - __uint_as_float(z & 0xFFFF0000u);
        float l3 = f.w - __uint_as_float(w & 0xFFFF0000u);
        uint2 l;
        asm("cvt.rn.bf16x2.f32 %0, %1, %2;" : "=r"(l.x) : "f"(l1), "f"(l0));
        asm("cvt.rn.bf16x2.f32 %0, %1, %2;" : "=r"(l.y) : "f"(l3), "f"(l2));
        hiP[i] = h;
        loP[i] = l;
    }
}

// split into two launches so gemm_mma(mode0) is the 4th launch (ncu captures #4)
__global__ void make_wt_qkv(const float* __restrict__ Wq, const float* __restrict__ Wkv) {
    int idx = blockIdx.x * 256 + threadIdx.x;
    if (idx >= 1152 * 384) return;
    int nrow = idx / 384, k = idx % 384;
    float v = (nrow < 384) ? Wq[(size_t)k * 384 + nrow]
                           : Wkv[(size_t)k * 768 + (nrow - 384)];
    uint32_t bits = __float_as_uint(v);
    float hf = __uint_as_float(bits & 0xFFFF0000u);
    g_WTh[idx] = __ushort_as_bfloat16((unsigned short)(bits >> 16));
    g_WTl[idx] = __float2bfloat16(v - hf);
}
__global__ void make_wt_proj(const float* __restrict__ Wproj) {
    int idx = blockIdx.x * 256 + threadIdx.x;
    if (idx >= 384 * 384) return;
    int nrow = idx / 384, k = idx % 384;
    float v = Wproj[(size_t)k * 384 + nrow];
    uint32_t bits = __float_as_uint(v);
    float hf = __uint_as_float(bits & 0xFFFF0000u);
    g_WTh[1152 * 384 + idx] = __ushort_as_bfloat16((unsigned short)(bits >> 16));
    g_WTl[1152 * 384 + idx] = __float2bfloat16(v - hf);
}

// ---------------- HMMA GEMM: 128x128 tile, K=384, 3-term split, 4-stage pipe ----
// chunk K=16; smem row stride 24 bf16 (48B) -> conflict-free ldmatrix + cp.async
#define CHROWB 48
#define BUFB   (128 * CHROWB)        // 6144 bytes per operand buffer
#define STAGEB (4 * BUFB)            // 24576 (Ah, Al, Bh, Bl)
#define SMEM_GEMM (4 * STAGEB)       // 98304

__global__ __launch_bounds__(256, 2)
void gemm_mma(const float* __restrict__ bias, float* __restrict__ out, int mode)
{
    extern __shared__ __align__(16) char smem[];
    const uint32_t sb = smem_u32(smem);
    const int tid = threadIdx.x, lane = tid & 31, wid = tid >> 5;
    const int warpM = wid & 1, warpN = wid >> 1;    // 2 x 4 warp grid
    const int rowBase = blockIdx.y * 128, colBase = blockIdx.x * 128;

    const __nv_bfloat16* Ahg = (mode == 0 ? g_Xh : g_Zh) + (size_t)rowBase * 384;
    const __nv_bfloat16* Alg = (mode == 0 ? g_Xl : g_Zl) + (size_t)rowBase * 384;
    const int brow = (mode == 0 ? 0 : 1152) + colBase;
    const __nv_bfloat16* Bhg = g_WTh + (size_t)brow * 384;
    const __nv_bfloat16* Blg = g_WTl + (size_t)brow * 384;

    // loader coords: 256 threads cover 128 rows x 2 16B-segments per buffer
    const int lr = tid >> 1, ls = tid & 1;
    const uint32_t lso = (uint32_t)(lr * CHROWB + ls * 16);

    float acc[4][4][4];
#pragma unroll
    for (int i = 0; i < 4; i++)
#pragma unroll
        for (int j = 0; j < 4; j++)
#pragma unroll
            for (int q = 0; q < 4; q++) acc[i][j][q] = 0.f;

    auto load_chunk = [&](int c, int stg) {
        const uint32_t base = sb + stg * STAGEB + lso;
        const size_t go = (size_t)lr * 384 + c * 16 + ls * 8;
        cp16(base,            Ahg + go);
        cp16(base + BUFB,     Alg + go);
        cp16(base + 2 * BUFB, Bhg + go);
        cp16(base + 3 * BUFB, Blg + go);
        asm volatile("cp.async.commit_group;" ::: "memory");
    };

    // ldmatrix per-lane addressing
    const int rA = lane & 15;
    const uint32_t cA16 = (lane & 16) ? 16u : 0u;
    const int rB = (lane & 7) + ((lane & 16) ? 8 : 0);
    const uint32_t cB16 = (lane & 8) ? 16u : 0u;

    load_chunk(0, 0);
    load_chunk(1, 1);
    load_chunk(2, 2);

    for (int c = 0; c < 24; c++) {
        if (c < 22)      asm volatile("cp.async.wait_group 2;" ::: "memory");
        else if (c == 22) asm volatile("cp.async.wait_group 1;" ::: "memory");
        else              asm volatile("cp.async.wait_group 0;" ::: "memory");
        __syncthreads();
        if (c + 3 < 24) load_chunk(c + 3, (c + 3) & 3);

        const uint32_t base = sb + (c & 3) * STAGEB;
        uint32_t ah[4][4], al[4][4], bx[4][2];
#pragma unroll
        for (int i = 0; i < 4; i++) {
            uint32_t addr = base + (uint32_t)((warpM * 64 + i * 16 + rA) * CHROWB) + cA16;
            ldm_x4(ah[i], addr);
            ldm_x4(al[i], addr + BUFB);
        }
#pragma unroll
        for (int jj = 0; jj < 2; jj++) {
            uint32_t rr[4];
            uint32_t addr = base + 2 * BUFB +
                (uint32_t)((warpN * 32 + jj * 16 + rB) * CHROWB) + cB16;
            ldm_x4(rr, addr);
            bx[2 * jj][0] = rr[0]; bx[2 * jj][1] = rr[1];
            bx[2 * jj + 1][0] = rr[2]; bx[2 * jj + 1][1] = rr[3];
        }
#pragma unroll
        for (int i = 0; i < 4; i++)
#pragma unroll
            for (int j = 0; j < 4; j++) mma16816(acc[i][j], ah[i], bx[j]);
#pragma unroll
        for (int i = 0; i < 4; i++)
#pragma unroll
            for (int j = 0; j < 4; j++) mma16816(acc[i][j], al[i], bx[j]);
#pragma unroll
        for (int jj = 0; jj < 2; jj++) {
            uint32_t rr[4];
            uint32_t addr = base + 3 * BUFB +
                (uint32_t)((warpN * 32 + jj * 16 + rB) * CHROWB) + cB16;
            ldm_x4(rr, addr);
            bx[2 * jj][0] = rr[0]; bx[2 * jj][1] = rr[1];
            bx[2 * jj + 1][0] = rr[2]; bx[2 * jj + 1][1] = rr[3];
        }
#pragma unroll
        for (int i = 0; i < 4; i++)
#pragma unroll
            for (int j = 0; j < 4; j++) mma16816(acc[i][j], ah[i], bx[j]);
    }

    // ---------------- epilogue ----------------
#pragma unroll
    for (int j = 0; j < 4; j++) {
        const int cg = colBase + warpN * 32 + j * 8 + 2 * (lane & 3);
#pragma unroll
        for (int i = 0; i < 4; i++) {
            const int m = rowBase + warpM * 64 + i * 16 + (lane >> 2);
            if (mode == 0) {
                int bb = m / NTOK, n = m % NTOK;
                float* dst;
                int d;
                if (cg < 384) {
                    dst = g_Q + (((size_t)bb * 12 + (cg >> 5)) * NTOK + n) * 32;
                    d = cg & 31;
                } else {
                    int j2 = cg - 384;
                    float* basep = (j2 >= 384) ? g_V : g_K;
                    dst = basep + (((size_t)bb * 12 + ((j2 >> 5) % 12)) * NTOK + n) * 32;
                    d = j2 & 31;
                }
                *(float2*)(dst + d)          = make_float2(acc[i][j][0], acc[i][j][1]);
                *(float2*)(dst + d + 8 * 32) = make_float2(acc[i][j][2], acc[i][j][3]);
            } else {
                float b0 = bias[cg], b1 = bias[cg + 1];
                *(float2*)(out + (size_t)m * 384 + cg) =
                    make_float2(acc[i][j][0] + b0, acc[i][j][1] + b1);
                *(float2*)(out + (size_t)(m + 8) * 384 + cg) =
                    make_float2(acc[i][j][2] + b0, acc[i][j][3] + b1);
            }
        }
    }
}

// ---------------- fused depthwise convs ------------------------------------------
__global__ void dwconv_fused(const float* __restrict__ w1, const float* __restrict__ b1,
                             const float* __restrict__ w2, const float* __restrict__ b2)
{
    int which = blockIdx.y % 3;          // 0=Q 1=K 2=V
    int op    = blockIdx.y / 3;          // 0=conv1 1=conv2
    const float* src = which == 0 ? g_Q : which == 1 ? g_K : g_V;
    int bg = blockIdx.x;                 // 0..127
    int b = bg >> 2, hl = bg & 3;

    if (op == 0) {
        float* dst = which == 0 ? g_Q1 : which == 1 ? g_K1 : g_V1;
        const float* s = src + ((size_t)(b * 12 + 4 + hl)) * NTOK * 32;
        float* d = dst + (size_t)bg * 784 * 32;
        for (int idx = threadIdx.x; idx < 784 * 32; idx += blockDim.x) {
            int c = idx & 31;
            int xy = idx >> 5;
            int xo = xy % 28, yo = xy / 28;
            float acc = b1[c];
#pragma unroll
            for (int i = 0; i < 2; i++)
#pragma unroll
                for (int j = 0; j < 2; j++)
                    acc = fmaf(s[((2 * yo + i) * 56 + 2 * xo + j) * 32 + c],
                               w1[(i * 2 + j) * 32 + c], acc);
            d[idx] = acc;
        }
    } else {
        float* dst = which == 0 ? g_Q2 : which == 1 ? g_K2 : g_V2;
        const float* s = src + ((size_t)(b * 12 + 8 + hl)) * NTOK * 32;
        float* d = dst + (size_t)bg * 196 * 32;
        for (int idx = threadIdx.x; idx < 196 * 32; idx += blockDim.x) {
            int c = idx & 31;
            int xy = idx >> 5;
            int xo = xy % 14, yo = xy / 14;
            float acc = b2[c];
#pragma unroll
            for (int i = 0; i < 2; i++) {
                int iy = 4 * yo - 1 + 2 * i;
                if (iy < 0 || iy >= 56) continue;
#pragma unroll
                for (int j = 0; j < 2; j++) {
                    int ix = 4 * xo - 1 + 2 * j;
                    if (ix < 0 || ix >= 56) continue;
                    acc = fmaf(s[(iy * 56 + ix) * 32 + c], w2[(i * 2 + j) * 32 + c], acc);
                }
            }
            d[idx] = acc;
        }
    }
}

// ---------------- windowed attention: reg-cached K, batched PV -------------------
__global__ __launch_bounds__(256)
void window_attn(int scaleId)
{
    __shared__ __align__(16) float sQ[49 * 36];
    __shared__ __align__(16) float sK[64 * 36];
    __shared__ __align__(16) float sV[49 * 36];

    const float *Qb, *Kb, *Vb;
    int side, nside, headOff, ntile, seq;
    if (scaleId == 0)      { Qb = g_Q;  Kb = g_K;  Vb = g_V;  side = 56; nside = 8; headOff = 0; ntile = 1;  seq = 3136; }
    else if (scaleId == 1) { Qb = g_Q1; Kb = g_K1; Vb = g_V1; side = 28; nside = 4; headOff = 4; ntile = 4;  seq = 784;  }
    else                   { Qb = g_Q2; Kb = g_K2; Vb = g_V2; side = 14; nside = 2; headOff = 8; ntile = 16; seq = 196;  }

    const int nwin = nside * nside;
    const int rg = blockIdx.x % nwin;
    const int hl = (blockIdx.x / nwin) & 3;
    const int b  = blockIdx.x / (nwin * 4);
    const int hb = rg / nside, wb = rg % nside;

    const int imgIdx = (scaleId == 0) ? (b * 12 + hl) : (b * 4 + hl);
    const float* Qp = Qb + (size_t)imgIdx * seq * 32;
    const float* Kp = Kb + (size_t)imgIdx * seq * 32;
    const float* Vp = Vb + (size_t)imgIdx * seq * 32;

    for (int idx = threadIdx.x; idx < 49 * 32; idx += 256) {
        int p = idx >> 5, k = idx & 31;
        int yy = hb * 7 + p / 7, xx = wb * 7 + p % 7;
        int off = (yy * side + xx) * 32 + k;
        sQ[p * 36 + k] = Qp[off];
        sK[p * 36 + k] = Kp[off];
        sV[p * 36 + k] = Vp[off];
    }
    // zero-fill K rows 49..63 (read speculatively by lane+32 path)
    for (int idx = threadIdx.x; idx < 15 * 36; idx += 256)
        sK[49 * 36 + idx] = 0.f;
    __syncthreads();

    const int lane = threadIdx.x & 31;
    const int warp = threadIdx.x >> 5;
    const float scale = 0.17677669529663687f;
    const bool hi = (lane < 17);

    // each lane caches K rows (lane) and (lane+32)
    float4 kA[8], kB[8];
#pragma unroll
    for (int j = 0; j < 8; j++) {
        kA[j] = *(const float4*)&sK[lane * 36 + 4 * j];
        kB[j] = *(const float4*)&sK[(lane + 32) * 36 + 4 * j];
    }

    float e0v[7], e1v[7], rinv[7], accv[7];
#pragma unroll
    for (int i = 0; i < 7; i++) { e0v[i] = 0.f; e1v[i] = 0.f; rinv[i] = 0.f; accv[i] = 0.f; }

#pragma unroll
    for (int i = 0; i < 7; i++) {
        int p = warp + 8 * i;
        if (p < 49) {
            float s0 = 0.f, s1 = 0.f;
#pragma unroll
            for (int j = 0; j < 8; j++) {
                float4 qv = *(const float4*)&sQ[p * 36 + 4 * j];
                s0 = fmaf(qv.x, kA[j].x, s0); s0 = fmaf(qv.y, kA[j].y, s0);
                s0 = fmaf(qv.z, kA[j].z, s0); s0 = fmaf(qv.w, kA[j].w, s0);
                s1 = fmaf(qv.x, kB[j].x, s1); s1 = fmaf(qv.y, kB[j].y, s1);
                s1 = fmaf(qv.z, kB[j].z, s1); s1 = fmaf(qv.w, kB[j].w, s1);
            }
            float t0 = s0 * scale;
            float t1 = s1 * scale;
            float m = hi ? fmaxf(t0, t1) : t0;
#pragma unroll
            for (int o = 16; o > 0; o >>= 1) m = fmaxf(m, __shfl_xor_sync(0xffffffffu, m, o));
            float e0 = __expf(t0 - m);
            float e1 = hi ? __expf(t1 - m) : 0.f;
            float sum = e0 + e1;
#pragma unroll
            for (int o = 16; o > 0; o >>= 1) sum += __shfl_xor_sync(0xffffffffu, sum, o);
            e0v[i] = e0;
            e1v[i] = e1;
            rinv[i] = 1.f / sum;
        }
    }

    // single PV pass shared across all of this warp's p-rows
    for (int q = 0; q < 49; q++) {
        float v = sV[q * 36 + lane];
        if (q < 32) {
#pragma unroll
            for (int i = 0; i < 7; i++) {
                float pq = __shfl_sync(0xffffffffu, e0v[i], q);
                accv[i] = fmaf(pq, v, accv[i]);
            }
        } else {
#pragma unroll
            for (int i = 0; i < 7; i++) {
                float pq = __shfl_sync(0xffffffffu, e1v[i], q - 32);
                accv[i] = fmaf(pq, v, accv[i]);
            }
        }
    }

#pragma unroll
    for (int i = 0; i < 7; i++) {
        int p = warp + 8 * i;
        if (p < 49) {
            float val = accv[i] * rinv[i];
            __nv_bfloat16 h = __float2bfloat16(val);
            __nv_bfloat16 l = __float2bfloat16(val - __bfloat162float(h));
            int col = (headOff + hl) * 32 + lane;
            for (int t = 0; t < ntile; t++) {
                int nout = (t * nwin + rg) * 49 + p;
                size_t off = ((size_t)b * NTOK + nout) * 384 + col;
                g_Zh[off] = h;
                g_Zl[off] = l;
            }
        }
    }
}

// ---------------- launch ---------------------------------------------------------
extern "C" void kernel_launch(void* const* d_in, const int* in_sizes, int n_in,
                              void* d_out, int out_size)
{
    const float* x     = (const float*)d_in[0];
    const float* Wq    = (const float*)d_in[1];
    const float* Wkv   = (const float*)d_in[2];
    const float* Wproj = (const float*)d_in[3];
    const float* bproj = (const float*)d_in[4];
    const float* c1w   = (const float*)d_in[5];
    const float* c1b   = (const float*)d_in[6];
    const float* c2w   = (const float*)d_in[7];
    const float* c2b   = (const float*)d_in[8];
    float* out = (float*)d_out;

    cudaFuncSetAttribute(gemm_mma, cudaFuncAttributeMaxDynamicSharedMemorySize, SMEM_GEMM);

    split_x<<<4704, 256>>>((const float4*)x);
    make_wt_qkv<<<1728, 256>>>(Wq, Wkv);
    make_wt_proj<<<576, 256>>>(Wproj);
    gemm_mma<<<dim3(9, 784), 256, SMEM_GEMM>>>(nullptr, nullptr, 0);   // 4th launch -> ncu
    dwconv_fused<<<dim3(128, 6), 256>>>(c1w, c1b, c2w, c2b);
    window_attn<<<32 * 4 * 64, 256>>>(0);
    window_attn<<<32 * 4 * 16, 256>>>(1);
    window_attn<<<32 * 4 * 4,  256>>>(2);
    gemm_mma<<<dim3(3, 784), 256, SMEM_GEMM>>>(bproj, out, 1);
}